// round 1
// baseline (speedup 1.0000x reference)
#include <cuda_runtime.h>
#include <cstdint>

// ---------------------------------------------------------------------------
// Problem constants (Swin window attention)
//   B_ = 2048 windows-batches, N = 49 tokens/window, H = 16 heads, D = 32,
//   C = 512 channels, nW = 64 masks.
// ---------------------------------------------------------------------------
#define B_TOT   2048
#define NTOK    49
#define NHEAD   16
#define HDIM    32
#define CDIM    512
#define NWIN    64
#define QK_SCALE 0.17677669529663687f   // 1/sqrt(32)

#define M_ROWS  (B_TOT * NTOK)          // 100352 = 784 * 128

// Scratch (device globals; allocation inside kernel_launch is forbidden)
__device__ float g_qkv[(size_t)M_ROWS * 3 * CDIM];   // (B*49, 1536)
__device__ float g_ao [(size_t)M_ROWS * CDIM];       // (B*49, 512) attn output

// ---------------------------------------------------------------------------
// GEMM: C[r][c] = sum_k A[r][k] * B[c][k] + bias[c]
// A: M x K row-major, B: N x K row-major (i.e. C = A * B^T), all fp32.
// 128x128 tile, BK=8, 256 threads, 8x8 microtile, packed fma.rn.f32x2.
// M % 128 == 0, N % 128 == 0, K % 8 == 0 assumed (true for this problem).
// ---------------------------------------------------------------------------
#define BM 128
#define BN 128
#define BK 8

__global__ __launch_bounds__(256, 2)
void sgemm_f32x2(const float* __restrict__ A, const float* __restrict__ B,
                 const float* __restrict__ bias, float* __restrict__ C,
                 int M, int N, int K)
{
    __shared__ float As[BK][BM + 4];
    __shared__ float Bs[BK][BN + 4];

    const int tid = threadIdx.x;
    const int tx  = tid & 15;      // 0..15 -> N direction (8 cols each)
    const int ty  = tid >> 4;      // 0..15 -> M direction (8 rows each)
    const int m0  = blockIdx.x * BM;
    const int n0  = blockIdx.y * BN;

    const float* Ag = A + (size_t)m0 * K;
    const float* Bg = B + (size_t)n0 * K;

    // 8x8 fp32 accumulator as 8x4 packed f32x2 pairs
    unsigned long long acc[8][4];
#pragma unroll
    for (int i = 0; i < 8; i++)
#pragma unroll
        for (int j = 0; j < 4; j++) acc[i][j] = 0ull;

    for (int k0 = 0; k0 < K; k0 += BK) {
        // Cooperative tile load: 1024 floats per tile, 4 scalars/thread.
        // Warp covers 4 rows x 8 contiguous floats -> 100% sector efficiency.
#pragma unroll
        for (int i = 0; i < 4; i++) {
            int idx = tid + i * 256;
            int r  = idx >> 3;
            int kk = idx & 7;
            As[kk][r] = Ag[(size_t)r * K + k0 + kk];
            Bs[kk][r] = Bg[(size_t)r * K + k0 + kk];
        }
        __syncthreads();

#pragma unroll
        for (int k = 0; k < BK; k++) {
            unsigned long long a2[8], b2[4];
#pragma unroll
            for (int i = 0; i < 8; i++) {
                float av = As[k][ty * 8 + i];
                asm("mov.b64 %0, {%1, %1};"
                    : "=l"(a2[i]) : "r"(__float_as_uint(av)));
            }
#pragma unroll
            for (int j = 0; j < 4; j++)
                b2[j] = *reinterpret_cast<const unsigned long long*>(
                            &Bs[k][tx * 8 + j * 2]);
#pragma unroll
            for (int i = 0; i < 8; i++)
#pragma unroll
                for (int j = 0; j < 4; j++)
                    asm("fma.rn.f32x2 %0, %1, %2, %0;"
                        : "+l"(acc[i][j]) : "l"(a2[i]), "l"(b2[j]));
        }
        __syncthreads();
    }

    // Epilogue: add bias, store as float2
#pragma unroll
    for (int i = 0; i < 8; i++) {
        const size_t r = (size_t)(m0 + ty * 8 + i);
#pragma unroll
        for (int j = 0; j < 4; j++) {
            float lo, hi;
            asm("mov.b64 {%0, %1}, %2;" : "=f"(lo), "=f"(hi) : "l"(acc[i][j]));
            const int c = n0 + tx * 8 + j * 2;
            float2 v = make_float2(lo + bias[c], hi + bias[c + 1]);
            *reinterpret_cast<float2*>(&C[r * N + c]) = v;
        }
    }
}

// ---------------------------------------------------------------------------
// Fused window attention: one CTA per (window b, head h).
//   scores = scale*q @ k^T + rpb_bias(h) + mask(b % 64)
//   P = softmax(scores); out = P @ v  -> g_ao[(b*49+n)*512 + h*32 + d]
// q/k/v gathered from g_qkv layout (B*49, [q(512) k(512) v(512)]).
// ---------------------------------------------------------------------------
__global__ __launch_bounds__(128)
void window_attn_kernel(const float* __restrict__ qkv,
                        const float* __restrict__ mask,
                        const float* __restrict__ rpb,
                        float* __restrict__ ao)
{
    const int b = blockIdx.x >> 4;
    const int h = blockIdx.x & 15;
    const int tid = threadIdx.x;

    __shared__ float qs[NTOK][HDIM + 1];   // +1 pad: conflict-free column reads
    __shared__ float ks[NTOK][HDIM + 1];
    __shared__ float vs[NTOK][HDIM + 1];
    __shared__ float sc[NTOK][NTOK];

    // Load q (pre-scaled), k, v for this (b, h)
    const size_t base = (size_t)b * NTOK * (3 * CDIM) + h * HDIM;
    for (int idx = tid; idx < NTOK * HDIM; idx += 128) {
        const int n = idx >> 5, d = idx & 31;
        const size_t off = base + (size_t)n * (3 * CDIM) + d;
        qs[n][d] = qkv[off] * QK_SCALE;
        ks[n][d] = qkv[off + CDIM];
        vs[n][d] = qkv[off + 2 * CDIM];
    }
    __syncthreads();

    // Scores + relative position bias + mask
    const float* mrow = mask + (size_t)(b & (NWIN - 1)) * NTOK * NTOK;
    for (int idx = tid; idx < NTOK * NTOK; idx += 128) {
        const int n = idx / NTOK;
        const int m = idx - n * NTOK;
        float s = 0.f;
#pragma unroll
        for (int d = 0; d < HDIM; d++) s += qs[n][d] * ks[m][d];
        const int ridx = (n / 7 - m / 7 + 6) * 13 + (n % 7 - m % 7 + 6);
        sc[n][m] = s + rpb[ridx * NHEAD + h] + mrow[idx];
    }
    __syncthreads();

    // Row softmax (one thread per row; 49 rows)
    if (tid < NTOK) {
        float mx = -1e30f;
#pragma unroll
        for (int m = 0; m < NTOK; m++) mx = fmaxf(mx, sc[tid][m]);
        float sum = 0.f;
#pragma unroll
        for (int m = 0; m < NTOK; m++) {
            float e = __expf(sc[tid][m] - mx);
            sc[tid][m] = e;
            sum += e;
        }
        const float inv = 1.f / sum;
#pragma unroll
        for (int m = 0; m < NTOK; m++) sc[tid][m] *= inv;
    }
    __syncthreads();

    // out = P @ v, write into proj-GEMM-friendly layout (B*49, 512)
    float* orow = ao + (size_t)b * NTOK * CDIM + h * HDIM;
    for (int idx = tid; idx < NTOK * HDIM; idx += 128) {
        const int n = idx >> 5, d = idx & 31;
        float o = 0.f;
#pragma unroll
        for (int m = 0; m < NTOK; m++) o += sc[n][m] * vs[m][d];
        orow[(size_t)n * CDIM + d] = o;
    }
}

// ---------------------------------------------------------------------------
// Launch: QKV GEMM -> fused attention -> proj GEMM (all graph-capturable)
// Inputs (metadata order): x, mask, rpb_table, qkv_w, qkv_b, proj_w, proj_b
// ---------------------------------------------------------------------------
extern "C" void kernel_launch(void* const* d_in, const int* in_sizes, int n_in,
                              void* d_out, int out_size)
{
    const float* x      = (const float*)d_in[0];
    const float* mask   = (const float*)d_in[1];
    const float* rpb    = (const float*)d_in[2];
    const float* qkv_w  = (const float*)d_in[3];
    const float* qkv_b  = (const float*)d_in[4];
    const float* proj_w = (const float*)d_in[5];
    const float* proj_b = (const float*)d_in[6];
    float* out = (float*)d_out;

    float *qkv_ptr = nullptr, *ao_ptr = nullptr;
    cudaGetSymbolAddress((void**)&qkv_ptr, g_qkv);
    cudaGetSymbolAddress((void**)&ao_ptr,  g_ao);

    // 1) QKV projection: (100352 x 512) * (1536 x 512)^T -> (100352 x 1536)
    {
        dim3 grid(M_ROWS / BM, (3 * CDIM) / BN);
        sgemm_f32x2<<<grid, 256>>>(x, qkv_w, qkv_b, qkv_ptr,
                                   M_ROWS, 3 * CDIM, CDIM);
    }

    // 2) Fused window attention: one CTA per (window, head)
    window_attn_kernel<<<B_TOT * NHEAD, 128>>>(qkv_ptr, mask, rpb, ao_ptr);

    // 3) Output projection: (100352 x 512) * (512 x 512)^T -> (100352 x 512)
    {
        dim3 grid(M_ROWS / BM, CDIM / BN);
        sgemm_f32x2<<<grid, 256>>>(ao_ptr, proj_w, proj_b, out,
                                   M_ROWS, CDIM, CDIM);
    }
}

// round 3
// speedup vs baseline: 1.9209x; 1.9209x over previous
#include <cuda_runtime.h>
#include <cuda_bf16.h>
#include <cstdint>

// ---------------------------------------------------------------------------
// Swin window attention: B_=2048, N=49, H=16, D=32, C=512, nW=64, fp32.
// GEMMs via mma.sync bf16 (split hi/lo, 3 products) — plain sm_100 PTX only
// (tcgen05 unavailable: harness compiles to compute_100 target).
// ---------------------------------------------------------------------------
#define B_TOT   2048
#define NTOK    49
#define NHEAD   16
#define HDIM    32
#define CDIM    512
#define NWIN    64
#define QK_SCALE 0.17677669529663687f
#define M_ROWS  (B_TOT * NTOK)          // 100352 = 784 * 128

__device__ float g_qkv[(size_t)M_ROWS * 3 * CDIM];
__device__ float g_ao [(size_t)M_ROWS * CDIM];

// ---------------------------------------------------------------------------
__device__ __forceinline__ uint32_t smem_u32(const void* p) {
    uint32_t a;
    asm("{ .reg .u64 t; cvta.to.shared.u64 t, %1; cvt.u32.u64 %0, t; }"
        : "=r"(a) : "l"(p));
    return a;
}

// fp32 pair -> (hi bf16x2, lo residual bf16x2)
__device__ __forceinline__ void cvt_pair(float2 v, uint32_t& hp, uint32_t& lp) {
    unsigned short h0 = __bfloat16_as_ushort(__float2bfloat16_rn(v.x));
    unsigned short h1 = __bfloat16_as_ushort(__float2bfloat16_rn(v.y));
    hp = (uint32_t)h0 | ((uint32_t)h1 << 16);
    float l0 = v.x - __uint_as_float((uint32_t)h0 << 16);
    float l1 = v.y - __uint_as_float((uint32_t)h1 << 16);
    asm("cvt.rn.bf16x2.f32 %0, %1, %2;" : "=r"(lp) : "f"(l1), "f"(l0));
}

#define LDSM4(r, addr) \
    asm volatile("ldmatrix.sync.aligned.m8n8.x4.shared.b16 {%0,%1,%2,%3}, [%4];" \
        : "=r"((r)[0]), "=r"((r)[1]), "=r"((r)[2]), "=r"((r)[3]) : "r"(addr))

#define MMA16816(d, a, b0, b1) \
    asm volatile("mma.sync.aligned.m16n8k16.row.col.f32.bf16.bf16.f32 " \
        "{%0,%1,%2,%3}, {%4,%5,%6,%7}, {%8,%9}, {%0,%1,%2,%3};" \
        : "+f"((d)[0]), "+f"((d)[1]), "+f"((d)[2]), "+f"((d)[3]) \
        : "r"((a)[0]), "r"((a)[1]), "r"((a)[2]), "r"((a)[3]), "r"(b0), "r"(b1))

// ---------------------------------------------------------------------------
// HMMA split-bf16 GEMM:  C[M,N] = A[M,K] * W[N,K]^T + bias
// CTA 128x128, BK=32 fp32/iter, 256 threads (8 warps, warp tile 64x32).
// smem rows: 32 bf16 payload, 80B stride (conflict-free ldmatrix phases).
// ---------------------------------------------------------------------------
#define BKF     32
#define ROWB    80
#define OFF_AH  0
#define OFF_AL  10240
#define OFF_BH  20480
#define OFF_BL  30720
#define SMEM_GEMM 40960

__global__ __launch_bounds__(256, 1)
void hmma_gemm(const float* __restrict__ A, const float* __restrict__ W,
               const float* __restrict__ bias, float* __restrict__ C,
               int N, int K)
{
    __shared__ char sm[SMEM_GEMM];
    const uint32_t sb = smem_u32(sm);

    const int tid = threadIdx.x;
    const int wid = tid >> 5, lid = tid & 31;
    const int warp_m = wid & 1;          // 0..1 -> 64-row halves
    const int warp_n = wid >> 1;         // 0..3 -> 32-col quarters
    const int m0 = blockIdx.y * 128;
    const int n0 = blockIdx.x * 128;

    const float* Ag = A + (size_t)m0 * K;
    const float* Wg = W + (size_t)n0 * K;
    const int r16 = tid >> 4;            // 0..15 (row within 16-row pass)
    const int c2  = tid & 15;            // float2 column (k-pair)

    // ldmatrix lane address components
    // A (x4): lanes 0-7 rows+0..7 @k0 | 8-15 rows+8..15 @k0 | 16-23 +0..7 @k8 | 24-31 +8..15 @k8
    const uint32_t aRow  = (uint32_t)(warp_m * 64 + (lid & 15));
    const uint32_t aKoff = (uint32_t)((lid >> 4) << 4);
    // B (x4): 0-7 n+0..7 @k0 | 8-15 n+0..7 @k8 | 16-23 n+8..15 @k0 | 24-31 n+8..15 @k8
    const uint32_t bRow  = (uint32_t)(warp_n * 32 + ((lid >> 4) << 3) + (lid & 7));
    const uint32_t bKoff = (uint32_t)(((lid >> 3) & 1) << 4);

    const uint32_t aHiB = sb + OFF_AH + aRow * ROWB + aKoff;
    const uint32_t aLoB = sb + OFF_AL + aRow * ROWB + aKoff;
    const uint32_t bHiB = sb + OFF_BH + bRow * ROWB + bKoff;
    const uint32_t bLoB = sb + OFF_BL + bRow * ROWB + bKoff;

    float acc[4][4][4];
#pragma unroll
    for (int i = 0; i < 4; i++)
#pragma unroll
        for (int j = 0; j < 4; j++)
#pragma unroll
            for (int e = 0; e < 4; e++) acc[i][j][e] = 0.f;

    float2 av[8], wv[8];
    // prefetch iter 0
#pragma unroll
    for (int p = 0; p < 8; p++) {
        av[p] = *(const float2*)(Ag + (size_t)(p * 16 + r16) * K + c2 * 2);
        wv[p] = *(const float2*)(Wg + (size_t)(p * 16 + r16) * K + c2 * 2);
    }

    const int iters = K / BKF;
    for (int i = 0; i < iters; i++) {
        __syncthreads();   // previous compute finished reading smem
#pragma unroll
        for (int p = 0; p < 8; p++) {
            const uint32_t ro = (uint32_t)(p * 16 + r16) * ROWB + c2 * 4;
            uint32_t hp, lp;
            cvt_pair(av[p], hp, lp);
            *(uint32_t*)(sm + OFF_AH + ro) = hp;
            *(uint32_t*)(sm + OFF_AL + ro) = lp;
            cvt_pair(wv[p], hp, lp);
            *(uint32_t*)(sm + OFF_BH + ro) = hp;
            *(uint32_t*)(sm + OFF_BL + ro) = lp;
        }
        __syncthreads();

        if (i + 1 < iters) {   // prefetch next iter (hides LDG under MMAs)
            const float* An = Ag + (i + 1) * BKF;
            const float* Wn = Wg + (i + 1) * BKF;
#pragma unroll
            for (int p = 0; p < 8; p++) {
                av[p] = *(const float2*)(An + (size_t)(p * 16 + r16) * K + c2 * 2);
                wv[p] = *(const float2*)(Wn + (size_t)(p * 16 + r16) * K + c2 * 2);
            }
        }

#pragma unroll
        for (int ks = 0; ks < 2; ks++) {
            const uint32_t ko = (uint32_t)(ks * 32);
            uint32_t ah[4][4], al[4][4], bh[2][4], bl[2][4];
#pragma unroll
            for (int t = 0; t < 4; t++) {
                LDSM4(ah[t], aHiB + ko + t * (16 * ROWB));
                LDSM4(al[t], aLoB + ko + t * (16 * ROWB));
            }
#pragma unroll
            for (int p = 0; p < 2; p++) {
                LDSM4(bh[p], bHiB + ko + p * (16 * ROWB));
                LDSM4(bl[p], bLoB + ko + p * (16 * ROWB));
            }
#pragma unroll
            for (int mi = 0; mi < 4; mi++)
#pragma unroll
                for (int nj = 0; nj < 4; nj++) {
                    const uint32_t* bph = bh[nj >> 1] + ((nj & 1) << 1);
                    const uint32_t* bpl = bl[nj >> 1] + ((nj & 1) << 1);
                    MMA16816(acc[mi][nj], ah[mi], bph[0], bph[1]);
                    MMA16816(acc[mi][nj], ah[mi], bpl[0], bpl[1]);
                    MMA16816(acc[mi][nj], al[mi], bph[0], bph[1]);
                }
        }
    }

    // Epilogue: d0,d1 -> (row, col..col+1); d2,d3 -> (row+8, ...)
    const int l4 = lid >> 2;
    const int lc = (lid & 3) * 2;
#pragma unroll
    for (int mi = 0; mi < 4; mi++) {
        const int row = m0 + warp_m * 64 + mi * 16 + l4;
#pragma unroll
        for (int nj = 0; nj < 4; nj++) {
            const int col = n0 + warp_n * 32 + nj * 8 + lc;
            const float b0 = bias[col], b1 = bias[col + 1];
            float2 v0 = make_float2(acc[mi][nj][0] + b0, acc[mi][nj][1] + b1);
            float2 v1 = make_float2(acc[mi][nj][2] + b0, acc[mi][nj][3] + b1);
            *(float2*)(C + (size_t)row * N + col)       = v0;
            *(float2*)(C + (size_t)(row + 8) * N + col) = v1;
        }
    }
}

// ---------------------------------------------------------------------------
// Fused window attention: one CTA per (window, head); warp-parallel softmax.
// ---------------------------------------------------------------------------
__global__ __launch_bounds__(128)
void window_attn_kernel(const float* __restrict__ qkv,
                        const float* __restrict__ mask,
                        const float* __restrict__ rpb,
                        float* __restrict__ ao)
{
    const int b = blockIdx.x >> 4;
    const int h = blockIdx.x & 15;
    const int tid = threadIdx.x;
    const int wid = tid >> 5, lid = tid & 31;

    __shared__ float qs[NTOK][HDIM + 1];
    __shared__ float ks[NTOK][HDIM + 1];
    __shared__ float vs[NTOK][HDIM + 1];
    __shared__ float sc[NTOK][NTOK];

    const size_t base = (size_t)b * NTOK * (3 * CDIM) + h * HDIM;
    for (int idx = tid; idx < NTOK * HDIM; idx += 128) {
        const int n = idx >> 5, d = idx & 31;
        const size_t off = base + (size_t)n * (3 * CDIM) + d;
        qs[n][d] = qkv[off] * QK_SCALE;
        ks[n][d] = qkv[off + CDIM];
        vs[n][d] = qkv[off + 2 * CDIM];
    }
    __syncthreads();

    const float* mrow = mask + (size_t)(b & (NWIN - 1)) * NTOK * NTOK;
    for (int idx = tid; idx < NTOK * NTOK; idx += 128) {
        const int n = idx / NTOK;
        const int m = idx - n * NTOK;
        float s = 0.f;
#pragma unroll
        for (int d = 0; d < HDIM; d++) s += qs[n][d] * ks[m][d];
        const int ridx = (n / 7 - m / 7 + 6) * 13 + (n % 7 - m % 7 + 6);
        sc[n][m] = s + rpb[ridx * NHEAD + h] + mrow[idx];
    }
    __syncthreads();

    // Warp-per-row softmax (4 warps cycle over 49 rows)
    for (int r = wid; r < NTOK; r += 4) {
        float v0 = sc[r][lid];
        float v1 = (lid < NTOK - 32) ? sc[r][lid + 32] : -3.0e38f;
        float mx = fmaxf(v0, v1);
#pragma unroll
        for (int o = 16; o; o >>= 1) mx = fmaxf(mx, __shfl_xor_sync(~0u, mx, o));
        float e0 = __expf(v0 - mx);
        float e1 = (lid < NTOK - 32) ? __expf(v1 - mx) : 0.f;
        float s = e0 + e1;
#pragma unroll
        for (int o = 16; o; o >>= 1) s += __shfl_xor_sync(~0u, s, o);
        const float inv = 1.f / s;
        sc[r][lid] = e0 * inv;
        if (lid < NTOK - 32) sc[r][lid + 32] = e1 * inv;
    }
    __syncthreads();

    float* orow = ao + (size_t)b * NTOK * CDIM + h * HDIM;
    for (int idx = tid; idx < NTOK * HDIM; idx += 128) {
        const int n = idx >> 5, d = idx & 31;
        float o = 0.f;
#pragma unroll
        for (int m = 0; m < NTOK; m++) o += sc[n][m] * vs[m][d];
        orow[(size_t)n * CDIM + d] = o;
    }
}

// ---------------------------------------------------------------------------
extern "C" void kernel_launch(void* const* d_in, const int* in_sizes, int n_in,
                              void* d_out, int out_size)
{
    const float* x      = (const float*)d_in[0];
    const float* mask   = (const float*)d_in[1];
    const float* rpb    = (const float*)d_in[2];
    const float* qkv_w  = (const float*)d_in[3];
    const float* qkv_b  = (const float*)d_in[4];
    const float* proj_w = (const float*)d_in[5];
    const float* proj_b = (const float*)d_in[6];
    float* out = (float*)d_out;

    float *qkv_ptr = nullptr, *ao_ptr = nullptr;
    cudaGetSymbolAddress((void**)&qkv_ptr, g_qkv);
    cudaGetSymbolAddress((void**)&ao_ptr,  g_ao);

    // 1) QKV projection: (100352 x 512) * (1536 x 512)^T
    hmma_gemm<<<dim3((3 * CDIM) / 128, M_ROWS / 128), 256>>>(
        x, qkv_w, qkv_b, qkv_ptr, 3 * CDIM, CDIM);

    // 2) Fused window attention
    window_attn_kernel<<<B_TOT * NHEAD, 128>>>(qkv_ptr, mask, rpb, ao_ptr);

    // 3) Output projection: (100352 x 512) * (512 x 512)^T
    hmma_gemm<<<dim3(CDIM / 128, M_ROWS / 128), 256>>>(
        ao_ptr, proj_w, proj_b, out, CDIM, CDIM);
}